// round 8
// baseline (speedup 1.0000x reference)
#include <cuda_runtime.h>
#include <cuda_bf16.h>
#include <cstdint>

// Shapes (fixed): pointcloud (4,16384,3) f32; keys (4096,3) f32; values (4096,64) f32
// Output f32: feats (65536,64) | ids (65536) | pointcloud (196608) = 4456448 elems

#define BN       65536
#define M_KEYS   4096
#define D_FEAT   64
#define PC_ELEMS 196608

#define FEATS_OFF 0
#define IDS_OFF   4194304
#define PC_OFF    4259840

// Uniform grid over key space.
#define G        32
#define NCELLS   (G * G * G)            // 32768
#define BOX      4.75f
#define CELLW    (2.0f * BOX / G)       // 0.296875
#define INVW     (1.0f / CELLW)
// Rounding slack: reference d2 chain abs error <= ~3e-5 for |p|,|k| <= ~6.
// MARGIN must exceed it; 1e-3 is >30x safety while visiting ~no extra cells.
#define MARGIN   1e-3f

typedef unsigned long long ull;

// Device scratch (no allocs allowed in kernel_launch).
__device__ int    g_khist[NCELLS];
__device__ int    g_phist[NCELLS];
__device__ int    g_kstart[NCELLS + 1];
__device__ int    g_kcur[NCELLS];
__device__ int    g_pstart[NCELLS + 1];   // kept for symmetry of scan kernel
__device__ int    g_pcur[NCELLS];
__device__ float4 g_skeys[M_KEYS];        // (x, y, z, ||k||^2), cell-sorted
__device__ int    g_skidx[M_KEYS];        // original key index
__device__ float4 g_spts[BN];             // (x, y, z, bitcast orig point idx)
__device__ int    g_ids[BN];              // result ids by original point index

__device__ __forceinline__ int cell_coord(float x) {
    int c = (int)floorf((x + BOX) * INVW);
    return min(max(c, 0), G - 1);
}

// ---------------------------------------------------------------------------
// K1: zero histograms.
// ---------------------------------------------------------------------------
__global__ void __launch_bounds__(256) zero_kernel() {
    int t = blockIdx.x * blockDim.x + threadIdx.x;
    if (t < NCELLS) { g_khist[t] = 0; g_phist[t] = 0; }
}

// ---------------------------------------------------------------------------
// K2: histogram points (all threads) and keys (first M_KEYS threads).
// ---------------------------------------------------------------------------
__global__ void __launch_bounds__(256) hist_kernel(
    const float* __restrict__ pc, const float* __restrict__ keys)
{
    int t = blockIdx.x * blockDim.x + threadIdx.x;
    if (t < BN) {
        int cx = cell_coord(pc[3*t+0]);
        int cy = cell_coord(pc[3*t+1]);
        int cz = cell_coord(pc[3*t+2]);
        atomicAdd(&g_phist[(cz * G + cy) * G + cx], 1);
    }
    if (t < M_KEYS) {
        int cx = cell_coord(keys[3*t+0]);
        int cy = cell_coord(keys[3*t+1]);
        int cz = cell_coord(keys[3*t+2]);
        atomicAdd(&g_khist[(cz * G + cy) * G + cx], 1);
    }
}

// ---------------------------------------------------------------------------
// K3: exclusive scan of both histograms. 2 blocks x 1024 threads;
// each thread owns 32 consecutive cells.
// ---------------------------------------------------------------------------
__global__ void __launch_bounds__(1024) scan_kernel() {
    const bool isK = (blockIdx.x == 0);
    int* hist  = isK ? g_khist  : g_phist;
    int* start = isK ? g_kstart : g_pstart;
    int* cur   = isK ? g_kcur   : g_pcur;

    int t = threadIdx.x;
    int s = 0;
#pragma unroll
    for (int i = 0; i < 32; ++i) s += hist[t * 32 + i];

    __shared__ int sm[1024];
    sm[t] = s;
    __syncthreads();
    for (int off = 1; off < 1024; off <<= 1) {
        int v = (t >= off) ? sm[t - off] : 0;
        __syncthreads();
        sm[t] += v;
        __syncthreads();
    }
    int run = sm[t] - s;   // exclusive prefix of this chunk

#pragma unroll
    for (int i = 0; i < 32; ++i) {
        int idx = t * 32 + i;
        start[idx] = run;
        cur[idx]   = run;
        run += hist[idx];
    }
    if (t == 1023) start[NCELLS] = run;
}

// ---------------------------------------------------------------------------
// K4: scatter points (all threads) and keys (first M_KEYS threads) into
// cell-sorted arrays. Within-cell order is nondeterministic (atomic), but the
// final argmin is order-invariant (lexicographic (d2, idx) min).
// ---------------------------------------------------------------------------
__global__ void __launch_bounds__(256) scatter_kernel(
    const float* __restrict__ pc, const float* __restrict__ keys)
{
    int t = blockIdx.x * blockDim.x + threadIdx.x;
    if (t < BN) {
        float x = pc[3*t+0], y = pc[3*t+1], z = pc[3*t+2];
        int c = (cell_coord(z) * G + cell_coord(y)) * G + cell_coord(x);
        int pos = atomicAdd(&g_pcur[c], 1);
        g_spts[pos] = make_float4(x, y, z, __int_as_float(t));
    }
    if (t < M_KEYS) {
        float kx = keys[3*t+0], ky = keys[3*t+1], kz = keys[3*t+2];
        // identical ksq chain as reference expansion
        float q = fmaf(kz, kz, fmaf(ky, ky, kx * kx));
        int c = (cell_coord(kz) * G + cell_coord(ky)) * G + cell_coord(kx);
        int pos = atomicAdd(&g_kcur[c], 1);
        g_skeys[pos] = make_float4(kx, ky, kz, q);
        g_skidx[pos] = t;
    }
}

// ---------------------------------------------------------------------------
// Per-axis distance from point coord to cell slab; boundary cells extend to
// +-inf on their outer face (covers clamped keys outside the box).
// ---------------------------------------------------------------------------
__device__ __forceinline__ float axis_dist(float p, int c) {
    float lo = (c == 0)     ? -1e30f : (-BOX + (float)c * CELLW);
    float hi = (c == G - 1) ?  1e30f : (-BOX + (float)(c + 1) * CELLW);
    return fmaxf(0.0f, fmaxf(lo - p, p - hi));
}

// ---------------------------------------------------------------------------
// K5: grid argmin. One thread per (cell-sorted) point -> warps are spatially
// coherent. Expanding Chebyshev shells; a cell/shell is skipped only when its
// geometric lower bound exceeds best + MARGIN (MARGIN >> d2 rounding error),
// so every key whose computed d2 could equal the final min IS evaluated with
// the exact reference chain. Lexicographic (d2, idx) update == jnp.argmin
// first-min semantics, independent of evaluation order.
// ---------------------------------------------------------------------------
__global__ void __launch_bounds__(256) argmin_grid_kernel()
{
    int t = blockIdx.x * blockDim.x + threadIdx.x;
    if (t >= BN) return;

    float4 p4 = g_spts[t];
    float px = p4.x, py = p4.y, pz = p4.z;
    int orig = __float_as_int(p4.w);
    float psq = fmaf(pz, pz, fmaf(py, py, px * px));

    int cx = cell_coord(px);
    int cy = cell_coord(py);
    int cz = cell_coord(pz);

    float best = __int_as_float(0x7f800000);  // +inf
    int   bidx = 0;

    for (int r = 0; r < G; ++r) {
        // Shell lower bound: any cell at Chebyshev distance r is at least
        // (r-1)*CELLW away from a point inside (or clamped outside) its cell.
        if (r >= 2) {
            float lbr = (float)(r - 1) * CELLW;
            if (lbr * lbr > best + MARGIN) break;
        }
        for (int dz = -r; dz <= r; ++dz) {
            int cz2 = cz + dz;
            if (cz2 < 0 || cz2 >= G) continue;
            int az = abs(dz);
            for (int dy = -r; dy <= r; ++dy) {
                int cy2 = cy + dy;
                if (cy2 < 0 || cy2 >= G) continue;
                int ayz = max(az, abs(dy));
                for (int dx = -r; dx <= r; ++dx) {
                    if (max(ayz, abs(dx)) != r) continue;   // shell only
                    int cx2 = cx + dx;
                    if (cx2 < 0 || cx2 >= G) continue;

                    float ax = axis_dist(px, cx2);
                    float ay = axis_dist(py, cy2);
                    float azd = axis_dist(pz, cz2);
                    float lb2 = fmaf(ax, ax, fmaf(ay, ay, azd * azd));
                    if (lb2 > best + MARGIN) continue;

                    int c = (cz2 * G + cy2) * G + cx2;
                    int s0 = g_kstart[c];
                    int s1 = g_kstart[c + 1];
                    for (int s = s0; s < s1; ++s) {
                        float4 k = g_skeys[s];
                        // exact reference chain
                        float cross = fmaf(pz, k.z, fmaf(py, k.y, px * k.x));
                        float d2 = fmaf(-2.0f, cross, psq) + k.w;
                        int j = g_skidx[s];
                        if (d2 < best || (d2 == best && j < bidx)) {
                            best = d2; bidx = j;
                        }
                    }
                }
            }
        }
    }

    g_ids[orig] = bidx;
}

// ---------------------------------------------------------------------------
// K6: gather values rows into feats + emit ids + copy pointcloud.
// 16 threads/point, float4 lanes.
// ---------------------------------------------------------------------------
__global__ void __launch_bounds__(256) gather_kernel(
    const float* __restrict__ pc,
    const float* __restrict__ values,
    float* __restrict__ out)
{
    int t = blockIdx.x * blockDim.x + threadIdx.x;

    if (t < PC_ELEMS / 4) {
        reinterpret_cast<float4*>(out + PC_OFF)[t] =
            reinterpret_cast<const float4*>(pc)[t];
    }

    int point = t >> 4;
    int q     = t & 15;
    if (point >= BN) return;

    int id = g_ids[point];
    if (q == 0) out[IDS_OFF + point] = (float)id;

    const float4* src = reinterpret_cast<const float4*>(values + (size_t)id * D_FEAT);
    float4* dst = reinterpret_cast<float4*>(out + FEATS_OFF + (size_t)point * D_FEAT);
    dst[q] = src[q];
}

// ---------------------------------------------------------------------------
extern "C" void kernel_launch(void* const* d_in, const int* in_sizes, int n_in,
                              void* d_out, int out_size) {
    const float* pc     = (const float*)d_in[0];
    const float* keys   = (const float*)d_in[1];
    const float* values = (const float*)d_in[2];
    float* out = (float*)d_out;

    zero_kernel<<<(NCELLS + 255) / 256, 256>>>();
    hist_kernel<<<(BN + 255) / 256, 256>>>(pc, keys);
    scan_kernel<<<2, 1024>>>();
    scatter_kernel<<<(BN + 255) / 256, 256>>>(pc, keys);
    argmin_grid_kernel<<<(BN + 255) / 256, 256>>>();
    gather_kernel<<<(BN * 16 + 255) / 256, 256>>>(pc, values, out);
}

// round 9
// speedup vs baseline: 5.7191x; 5.7191x over previous
#include <cuda_runtime.h>
#include <cuda_bf16.h>
#include <cstdint>

// Shapes (fixed): pointcloud (4,16384,3) f32; keys (4096,3) f32; values (4096,64) f32
// Output f32: feats (65536,64) | ids (65536) | pointcloud (196608) = 4456448 elems

#define BN       65536
#define M_KEYS   4096
#define D_FEAT   64
#define PC_ELEMS 196608

#define FEATS_OFF 0
#define IDS_OFF   4194304
#define PC_OFF    4259840

// Uniform grid over key space. G=16: ~16 pts/cell avg (core ~870) -> coherent
// warps after sort; kstart (16KB) L1-resident.
#define G        16
#define NCELLS   (G * G * G)            // 4096
#define BOX      4.75f
#define CELLW    (2.0f * BOX / G)       // 0.59375
#define INVW     (1.0f / CELLW)
// Rounding slack: reference d2 chain abs error <= ~3e-5 for |p|,|k| <= ~6.
#define MARGIN   1e-3f

typedef unsigned long long ull;

// Device scratch (no allocs allowed in kernel_launch).
__device__ int    g_khist[NCELLS];
__device__ int    g_phist[NCELLS];
__device__ int    g_kstart[NCELLS + 1];
__device__ int    g_kcur[NCELLS];
__device__ int    g_pstart[NCELLS + 1];
__device__ int    g_pcur[NCELLS];
__device__ float4 g_skeys[M_KEYS];        // (x, y, z, ||k||^2), cell-sorted
__device__ int    g_skidx[M_KEYS];        // original key index
__device__ float4 g_spts[BN];             // (x, y, z, bitcast orig point idx)
__device__ int    g_ids[BN];              // result ids by original point index

__device__ __forceinline__ int cell_coord(float x) {
    int c = (int)floorf((x + BOX) * INVW);
    return min(max(c, 0), G - 1);
}

// ---------------------------------------------------------------------------
// K1: zero histograms.
// ---------------------------------------------------------------------------
__global__ void __launch_bounds__(256) zero_kernel() {
    int t = blockIdx.x * blockDim.x + threadIdx.x;
    if (t < NCELLS) { g_khist[t] = 0; g_phist[t] = 0; }
}

// ---------------------------------------------------------------------------
// K2: histogram points (all threads) and keys (first M_KEYS threads).
// ---------------------------------------------------------------------------
__global__ void __launch_bounds__(256) hist_kernel(
    const float* __restrict__ pc, const float* __restrict__ keys)
{
    int t = blockIdx.x * blockDim.x + threadIdx.x;
    if (t < BN) {
        int cx = cell_coord(pc[3*t+0]);
        int cy = cell_coord(pc[3*t+1]);
        int cz = cell_coord(pc[3*t+2]);
        atomicAdd(&g_phist[(cz * G + cy) * G + cx], 1);
    }
    if (t < M_KEYS) {
        int cx = cell_coord(keys[3*t+0]);
        int cy = cell_coord(keys[3*t+1]);
        int cz = cell_coord(keys[3*t+2]);
        atomicAdd(&g_khist[(cz * G + cy) * G + cx], 1);
    }
}

// ---------------------------------------------------------------------------
// K3: exclusive scan of both histograms. 2 blocks x 1024 threads;
// each thread owns 4 consecutive cells.
// ---------------------------------------------------------------------------
__global__ void __launch_bounds__(1024) scan_kernel() {
    const bool isK = (blockIdx.x == 0);
    int* hist  = isK ? g_khist  : g_phist;
    int* start = isK ? g_kstart : g_pstart;
    int* cur   = isK ? g_kcur   : g_pcur;

    int t = threadIdx.x;
    int s = 0;
#pragma unroll
    for (int i = 0; i < 4; ++i) s += hist[t * 4 + i];

    __shared__ int sm[1024];
    sm[t] = s;
    __syncthreads();
    for (int off = 1; off < 1024; off <<= 1) {
        int v = (t >= off) ? sm[t - off] : 0;
        __syncthreads();
        sm[t] += v;
        __syncthreads();
    }
    int run = sm[t] - s;   // exclusive prefix of this chunk

#pragma unroll
    for (int i = 0; i < 4; ++i) {
        int idx = t * 4 + i;
        start[idx] = run;
        cur[idx]   = run;
        run += hist[idx];
    }
    if (t == 1023) start[NCELLS] = run;
}

// ---------------------------------------------------------------------------
// K4: scatter points and keys into cell-sorted arrays. Within-cell order is
// nondeterministic (atomic), but the final argmin is order-invariant.
// ---------------------------------------------------------------------------
__global__ void __launch_bounds__(256) scatter_kernel(
    const float* __restrict__ pc, const float* __restrict__ keys)
{
    int t = blockIdx.x * blockDim.x + threadIdx.x;
    if (t < BN) {
        float x = pc[3*t+0], y = pc[3*t+1], z = pc[3*t+2];
        int c = (cell_coord(z) * G + cell_coord(y)) * G + cell_coord(x);
        int pos = atomicAdd(&g_pcur[c], 1);
        g_spts[pos] = make_float4(x, y, z, __int_as_float(t));
    }
    if (t < M_KEYS) {
        float kx = keys[3*t+0], ky = keys[3*t+1], kz = keys[3*t+2];
        float q = fmaf(kz, kz, fmaf(ky, ky, kx * kx));   // identical ksq chain
        int c = (cell_coord(kz) * G + cell_coord(ky)) * G + cell_coord(kx);
        int pos = atomicAdd(&g_kcur[c], 1);
        g_skeys[pos] = make_float4(kx, ky, kz, q);
        g_skidx[pos] = t;
    }
}

// ---------------------------------------------------------------------------
// Per-axis distance to cell slab; boundary cells extend to +-inf outward
// (covers clamped coords outside the box).
// ---------------------------------------------------------------------------
__device__ __forceinline__ float axis_dist(float p, int c) {
    float lo = (c == 0)     ? -1e30f : (-BOX + (float)c * CELLW);
    float hi = (c == G - 1) ?  1e30f : (-BOX + (float)(c + 1) * CELLW);
    return fmaxf(0.0f, fmaxf(lo - p, p - hi));
}

// ---------------------------------------------------------------------------
// Exact scan of one cell's key list with the reference d2 chain and
// lexicographic (d2, idx) update.
// ---------------------------------------------------------------------------
__device__ __forceinline__ void scan_cell(
    int c, float px, float py, float pz, float psq,
    float& best, int& bidx)
{
    int s0 = g_kstart[c];
    int s1 = g_kstart[c + 1];
    for (int s = s0; s < s1; ++s) {
        float4 k = g_skeys[s];
        float cross = fmaf(pz, k.z, fmaf(py, k.y, px * k.x));
        float d2 = fmaf(-2.0f, cross, psq) + k.w;
        int j = g_skidx[s];
        if (d2 < best || (d2 == best && j < bidx)) { best = d2; bidx = j; }
    }
}

// ---------------------------------------------------------------------------
// K5: grid argmin over cell-sorted points (warp-coherent in the dense core).
// Pass 1: own cell (sets best early). Pass 2: remaining 26 neighbors with
// lb2 pruning. Pass 3: rare expanding shells (tail points only).
// Skip rule: lb2 > best + MARGIN, MARGIN >> d2 rounding error => every key
// whose computed d2 could equal/beat the running min IS evaluated exactly.
// ---------------------------------------------------------------------------
__global__ void __launch_bounds__(256) argmin_grid_kernel()
{
    int t = blockIdx.x * blockDim.x + threadIdx.x;
    if (t >= BN) return;

    float4 p4 = g_spts[t];
    float px = p4.x, py = p4.y, pz = p4.z;
    int orig = __float_as_int(p4.w);
    float psq = fmaf(pz, pz, fmaf(py, py, px * px));

    int cx = cell_coord(px);
    int cy = cell_coord(py);
    int cz = cell_coord(pz);

    float best = __int_as_float(0x7f800000);  // +inf
    int   bidx = 0;

    // Pass 1: own cell.
    scan_cell((cz * G + cy) * G + cx, px, py, pz, psq, best, bidx);

    // Pass 2: 26 neighbors with lb pruning.
#pragma unroll
    for (int dz = -1; dz <= 1; ++dz) {
        int cz2 = cz + dz;
        if (cz2 < 0 || cz2 >= G) continue;
        float azd = axis_dist(pz, cz2);
#pragma unroll
        for (int dy = -1; dy <= 1; ++dy) {
            int cy2 = cy + dy;
            if (cy2 < 0 || cy2 >= G) continue;
            float ay = axis_dist(py, cy2);
#pragma unroll
            for (int dx = -1; dx <= 1; ++dx) {
                if (dx == 0 && dy == 0 && dz == 0) continue;
                int cx2 = cx + dx;
                if (cx2 < 0 || cx2 >= G) continue;
                float ax = axis_dist(px, cx2);
                float lb2 = fmaf(ax, ax, fmaf(ay, ay, azd * azd));
                if (lb2 > best + MARGIN) continue;
                scan_cell((cz2 * G + cy2) * G + cx2, px, py, pz, psq, best, bidx);
            }
        }
    }

    // Pass 3: expanding shells for points not resolved locally (rare).
    for (int r = 2; r < G; ++r) {
        float lbr = (float)(r - 1) * CELLW;
        if (lbr * lbr > best + MARGIN) break;
        int zlo = max(cz - r, 0), zhi = min(cz + r, G - 1);
        for (int cz2 = zlo; cz2 <= zhi; ++cz2) {
            int az = abs(cz2 - cz);
            float azd = axis_dist(pz, cz2);
            int ylo = max(cy - r, 0), yhi = min(cy + r, G - 1);
            for (int cy2 = ylo; cy2 <= yhi; ++cy2) {
                int ayz = max(az, abs(cy2 - cy));
                float ay = axis_dist(py, cy2);
                // If this (z,y) line can't reach Chebyshev r, only the two
                // x-extremes belong to the shell; otherwise whole x range.
                int xlo = max(cx - r, 0), xhi = min(cx + r, G - 1);
                for (int cx2 = xlo; cx2 <= xhi; ++cx2) {
                    if (max(ayz, abs(cx2 - cx)) != r) continue;   // shell only
                    float ax = axis_dist(px, cx2);
                    float lb2 = fmaf(ax, ax, fmaf(ay, ay, azd * azd));
                    if (lb2 > best + MARGIN) continue;
                    scan_cell((cz2 * G + cy2) * G + cx2, px, py, pz, psq, best, bidx);
                }
            }
        }
    }

    g_ids[orig] = bidx;
}

// ---------------------------------------------------------------------------
// K6: gather values rows into feats + emit ids + copy pointcloud.
// ---------------------------------------------------------------------------
__global__ void __launch_bounds__(256) gather_kernel(
    const float* __restrict__ pc,
    const float* __restrict__ values,
    float* __restrict__ out)
{
    int t = blockIdx.x * blockDim.x + threadIdx.x;

    if (t < PC_ELEMS / 4) {
        reinterpret_cast<float4*>(out + PC_OFF)[t] =
            reinterpret_cast<const float4*>(pc)[t];
    }

    int point = t >> 4;
    int q     = t & 15;
    if (point >= BN) return;

    int id = g_ids[point];
    if (q == 0) out[IDS_OFF + point] = (float)id;

    const float4* src = reinterpret_cast<const float4*>(values + (size_t)id * D_FEAT);
    float4* dst = reinterpret_cast<float4*>(out + FEATS_OFF + (size_t)point * D_FEAT);
    dst[q] = src[q];
}

// ---------------------------------------------------------------------------
extern "C" void kernel_launch(void* const* d_in, const int* in_sizes, int n_in,
                              void* d_out, int out_size) {
    const float* pc     = (const float*)d_in[0];
    const float* keys   = (const float*)d_in[1];
    const float* values = (const float*)d_in[2];
    float* out = (float*)d_out;

    zero_kernel<<<(NCELLS + 255) / 256, 256>>>();
    hist_kernel<<<(BN + 255) / 256, 256>>>(pc, keys);
    scan_kernel<<<2, 1024>>>();
    scatter_kernel<<<(BN + 255) / 256, 256>>>(pc, keys);
    argmin_grid_kernel<<<(BN + 255) / 256, 256>>>();
    gather_kernel<<<(BN * 16 + 255) / 256, 256>>>(pc, values, out);
}